// round 16
// baseline (speedup 1.0000x reference)
#include <cuda_runtime.h>
#include <cuda_bf16.h>
#include <cstdint>

// DynamicSparseAttention: B=4,H=16,S=2048,D=64
// d_out layout (f32): [out: BH*S*D][attn: BH*S*S][tau: BH*S]
#define S_LEN 2048
#define D_DIM 64
#define BH    64
#define NELEM (BH * S_LEN * D_DIM)                 // 8388608
#define SELEM ((size_t)BH * S_LEN * S_LEN)         // 268435456

// pre-split bf16 hi/lo scratch for Q/K; f32(tf32-rounded) transposed V
__device__ __align__(16) __nv_bfloat16 g_qhi[NELEM];
__device__ __align__(16) __nv_bfloat16 g_qlo[NELEM];
__device__ __align__(16) __nv_bfloat16 g_khi[NELEM];
__device__ __align__(16) __nv_bfloat16 g_klo[NELEM];
__device__ __align__(16) float g_vt[NELEM];        // [bh][n=64][k=2048]

// ---------------------------------------------------------------- helpers
__device__ __forceinline__ uint32_t smem_u32(const void* p) {
    uint32_t a;
    asm("{ .reg .u64 t; cvta.to.shared.u64 t, %1; cvt.u32.u64 %0, t; }"
        : "=r"(a) : "l"(p));
    return a;
}

// 128B-row tile, 16B-chunk XOR swizzle
__device__ __forceinline__ uint32_t toff(int r, int ch) {
    return (uint32_t)(r * 128 + ((ch ^ (r & 7)) << 4));
}

__device__ __forceinline__ void ldmx4(uint32_t* r, uint32_t a) {
    asm volatile("ldmatrix.sync.aligned.m8n8.x4.shared.b16 {%0,%1,%2,%3}, [%4];"
        : "=r"(r[0]), "=r"(r[1]), "=r"(r[2]), "=r"(r[3]) : "r"(a));
}
__device__ __forceinline__ void mma_bf16(float* c, const uint32_t* a, const uint32_t* b) {
    asm volatile(
        "mma.sync.aligned.m16n8k16.row.col.f32.bf16.bf16.f32 "
        "{%0,%1,%2,%3}, {%4,%5,%6,%7}, {%8,%9}, {%0,%1,%2,%3};"
        : "+f"(c[0]), "+f"(c[1]), "+f"(c[2]), "+f"(c[3])
        : "r"(a[0]), "r"(a[1]), "r"(a[2]), "r"(a[3]), "r"(b[0]), "r"(b[1]));
}
__device__ __forceinline__ uint32_t cvt_tf32(float f) {
    uint32_t u;
    asm("cvt.rna.tf32.f32 %0, %1;" : "=r"(u) : "f"(f));
    return u;
}
__device__ __forceinline__ float round_tf32(float f) {
    return __uint_as_float(cvt_tf32(f));
}
__device__ __forceinline__ void mma_tf32(float* c, const uint32_t* a,
                                         uint32_t b0, uint32_t b1) {
    asm volatile(
        "mma.sync.aligned.m16n8k8.row.col.f32.tf32.tf32.f32 "
        "{%0,%1,%2,%3}, {%4,%5,%6,%7}, {%8,%9}, {%0,%1,%2,%3};"
        : "+f"(c[0]), "+f"(c[1]), "+f"(c[2]), "+f"(c[3])
        : "r"(a[0]), "r"(a[1]), "r"(a[2]), "r"(a[3]), "r"(b0), "r"(b1));
}

__device__ __forceinline__ void cpa16(uint32_t dst, const void* src) {
    asm volatile("cp.async.cg.shared.global [%0], [%1], 16;"
                 :: "r"(dst), "l"(__cvta_generic_to_global(src)));
}
__device__ __forceinline__ void cpa_commit() {
    asm volatile("cp.async.commit_group;");
}
template <int N>
__device__ __forceinline__ void cpa_wait() {
    asm volatile("cp.async.wait_group %0;" :: "n"(N));
}

__device__ __forceinline__ uint32_t bfpair(float a, float b) {
    __nv_bfloat162 t;
    t.x = __float2bfloat16(a);
    t.y = __float2bfloat16(b);
    return *reinterpret_cast<uint32_t*>(&t);
}
__device__ __forceinline__ void split2(float a, float b, uint32_t& h, uint32_t& l) {
    __nv_bfloat16 ha = __float2bfloat16(a), hb = __float2bfloat16(b);
    __nv_bfloat162 hp; hp.x = ha; hp.y = hb;
    h = *reinterpret_cast<uint32_t*>(&hp);
    l = bfpair(a - __bfloat162float(ha), b - __bfloat162float(hb));
}
__device__ __forceinline__ void split4(float4 f, uint2& hi, uint2& lo) {
    split2(f.x, f.y, hi.x, lo.x);
    split2(f.z, f.w, hi.y, lo.y);
}

// -------------------------------------------------------------------------
// Kernel 0: pre-split Q*0.125, K into bf16 hi/lo; transpose V -> g_vt
// (tf32-rounded, so AV needs no cvt).
// -------------------------------------------------------------------------
__global__ __launch_bounds__(256) void dsa_prep(
    const float* __restrict__ q, const float* __restrict__ k,
    const float* __restrict__ v)
{
    const int stride = gridDim.x * 256;
    const float4* q4 = (const float4*)q;
    const float4* k4 = (const float4*)k;
    const float4* v4 = (const float4*)v;
    uint2* qh = (uint2*)g_qhi; uint2* ql = (uint2*)g_qlo;
    uint2* kh = (uint2*)g_khi; uint2* kl = (uint2*)g_klo;

    for (int i = blockIdx.x * 256 + threadIdx.x; i < NELEM / 4; i += stride) {
        float4 fq = q4[i];
        fq.x *= 0.125f; fq.y *= 0.125f; fq.z *= 0.125f; fq.w *= 0.125f;
        uint2 hi, lo;
        split4(fq, hi, lo); qh[i] = hi; ql[i] = lo;
        split4(k4[i], hi, lo); kh[i] = hi; kl[i] = lo;

        // V transpose + tf32 rounding: i indexes [bh][kk][n4] float4
        float4 fv = v4[i];
        int bh = i >> 15;                 // / (2048*16)
        int rem = i & 32767;
        int kk = rem >> 4;
        int n4 = rem & 15;
        float* vt = g_vt + ((size_t)bh * 64 + n4 * 4) * S_LEN + kk;
        vt[0]          = round_tf32(fv.x);
        vt[S_LEN]      = round_tf32(fv.y);
        vt[2 * S_LEN]  = round_tf32(fv.z);
        vt[3 * S_LEN]  = round_tf32(fv.w);
    }
}

// -------------------------------------------------------------------------
// Kernel 1: raw scores = (Q*scale) K^T -> f32 attn buffer (pre-softmax).
// CTA = 128-row q-stripe over 16 k-tiles of 128. 512 thr, 16 warps (4m x 4n).
// A frags cached in regs; K tiles via cp.async double-buffered. SMEM 96KB.
// bf16 hi/lo 3-term split. Streaming stores (.cs) — read once much later.
// -------------------------------------------------------------------------
#define SC_SMEM 98304
__global__ __launch_bounds__(512) void dsa_scores_kernel(float* __restrict__ attn)
{
    extern __shared__ __align__(16) char sm[];
    const uint32_t sb = smem_u32(sm);
    const uint32_t QHI = 0, QLO = 16384;      // K bufs at 32768 + b*32768

    const int tid = threadIdx.x, lane = tid & 31, wid = tid >> 5;
    const int qt = blockIdx.x, bh = blockIdx.y;

    const __nv_bfloat16* Qh = g_qhi + ((size_t)bh * S_LEN + (size_t)qt * 128) * D_DIM;
    const __nv_bfloat16* Ql = g_qlo + ((size_t)bh * S_LEN + (size_t)qt * 128) * D_DIM;
    const __nv_bfloat16* Kh = g_khi + (size_t)bh * S_LEN * D_DIM;
    const __nv_bfloat16* Kl = g_klo + (size_t)bh * S_LEN * D_DIM;

    // group 0: Q hi/lo + K tile 0
    #pragma unroll
    for (int i = 0; i < 2; i++) {
        int idx = tid + i * 512;
        int r = idx >> 3, ch = idx & 7;
        uint32_t o = toff(r, ch);
        cpa16(sb + QHI + o, Qh + r * 64 + ch * 8);
        cpa16(sb + QLO + o, Ql + r * 64 + ch * 8);
        cpa16(sb + 32768 + o, Kh + r * 64 + ch * 8);
        cpa16(sb + 32768 + 16384 + o, Kl + r * 64 + ch * 8);
    }
    cpa_commit();
    // group 1: K tile 1
    #pragma unroll
    for (int i = 0; i < 2; i++) {
        int idx = tid + i * 512;
        int r = idx >> 3, ch = idx & 7;
        uint32_t o = toff(r, ch);
        cpa16(sb + 65536 + o, Kh + (size_t)(128 + r) * 64 + ch * 8);
        cpa16(sb + 65536 + 16384 + o, Kl + (size_t)(128 + r) * 64 + ch * 8);
    }
    cpa_commit();
    cpa_wait<1>();
    __syncthreads();

    const int wm = wid >> 2, wn = wid & 3;
    const int alr = lane & 7, alm = (lane >> 3) & 1, alk = lane >> 4;
    const int brow_off = ((lane >> 4) << 3) + (lane & 7);
    const int bchk_off = (lane >> 3) & 1;

    // A fragments cached in registers for the whole kernel
    uint32_t ah[4][2][4], al[4][2][4];
    #pragma unroll
    for (int ks = 0; ks < 4; ks++)
        #pragma unroll
        for (int mi = 0; mi < 2; mi++) {
            int row = wm * 32 + mi * 16 + alr + alm * 8;
            uint32_t o = toff(row, ks * 2 + alk);
            ldmx4(ah[ks][mi], sb + QHI + o);
            ldmx4(al[ks][mi], sb + QLO + o);
        }

    const int qr = lane >> 2, qc = (lane & 3) * 2;
    float* abase = attn + ((size_t)bh * S_LEN + (size_t)qt * 128) * S_LEN;

    for (int t = 0; t < 16; t++) {
        const uint32_t KB = sb + 32768 + (uint32_t)(t & 1) * 32768;

        float acc[2][4][4] = {};
        #pragma unroll
        for (int ks = 0; ks < 4; ks++) {
            uint32_t bh_[2][4], bl_[2][4];
            #pragma unroll
            for (int nj = 0; nj < 2; nj++) {
                int row = wn * 32 + nj * 16 + brow_off;
                uint32_t o = toff(row, ks * 2 + bchk_off);
                ldmx4(bh_[nj], KB + o);
                ldmx4(bl_[nj], KB + 16384 + o);
            }
            #pragma unroll
            for (int mi = 0; mi < 2; mi++)
                #pragma unroll
                for (int nj = 0; nj < 2; nj++) {
                    mma_bf16(acc[mi][2*nj],   ah[ks][mi], bh_[nj]);
                    mma_bf16(acc[mi][2*nj+1], ah[ks][mi], bh_[nj] + 2);
                }
            #pragma unroll
            for (int mi = 0; mi < 2; mi++)
                #pragma unroll
                for (int nj = 0; nj < 2; nj++) {
                    mma_bf16(acc[mi][2*nj],   ah[ks][mi], bl_[nj]);
                    mma_bf16(acc[mi][2*nj+1], ah[ks][mi], bl_[nj] + 2);
                }
            #pragma unroll
            for (int mi = 0; mi < 2; mi++)
                #pragma unroll
                for (int nj = 0; nj < 2; nj++) {
                    mma_bf16(acc[mi][2*nj],   al[ks][mi], bh_[nj]);
                    mma_bf16(acc[mi][2*nj+1], al[ks][mi], bh_[nj] + 2);
                }
        }

        float* base = abase + (size_t)t * 128;
        #pragma unroll
        for (int mi = 0; mi < 2; mi++) {
            #pragma unroll
            for (int ni = 0; ni < 4; ni++) {
                int row = wm * 32 + mi * 16 + qr;
                int col = wn * 32 + ni * 8 + qc;
                float2 v0 = make_float2(acc[mi][ni][0], acc[mi][ni][1]);
                float2 v1 = make_float2(acc[mi][ni][2], acc[mi][ni][3]);
                __stcs((float2*)(base + (size_t)row * S_LEN + col), v0);
                __stcs((float2*)(base + (size_t)(row + 8) * S_LEN + col), v1);
            }
        }
        __syncthreads();

        if (t + 2 < 16) {
            const __nv_bfloat16* th = Kh + (size_t)(t + 2) * 128 * 64;
            const __nv_bfloat16* tl = Kl + (size_t)(t + 2) * 128 * 64;
            uint32_t dst = sb + 32768 + (uint32_t)(t & 1) * 32768;
            #pragma unroll
            for (int i = 0; i < 2; i++) {
                int idx = tid + i * 512;
                int r = idx >> 3, ch = idx & 7;
                uint32_t o = toff(r, ch);
                cpa16(dst + o, th + r * 64 + ch * 8);
                cpa16(dst + 16384 + o, tl + r * 64 + ch * 8);
            }
            cpa_commit();
            cpa_wait<1>();
        } else {
            cpa_wait<0>();
        }
        __syncthreads();
    }
}

// -------------------------------------------------------------------------
// Kernel 2: per-row variance (ddof=1) -> tau -> softmax(scores/tau) in place.
// Warp-per-row, row in registers. Output values tf32-ROUNDED (still valid
// f32; lets AV consume raw bits with zero cvt). Streaming ld/st hints.
// -------------------------------------------------------------------------
__global__ __launch_bounds__(256, 2) void dsa_softvar_kernel(
    float* __restrict__ attn, float* __restrict__ tau_out)
{
    const int lane = threadIdx.x & 31;
    const int w = threadIdx.x >> 5;
    const size_t row = (size_t)blockIdx.x * 8 + w;
    float4* r4 = (float4*)(attn + row * S_LEN);

    float4 d[16];
    float sum = 0.f, sq = 0.f, mx = -3.402823466e38f;
    #pragma unroll
    for (int i = 0; i < 16; i++) {
        float4 f = __ldcs(&r4[lane + 32 * i]);
        d[i] = f;
        sum += f.x + f.y + f.z + f.w;
        sq = fmaf(f.x, f.x, sq); sq = fmaf(f.y, f.y, sq);
        sq = fmaf(f.z, f.z, sq); sq = fmaf(f.w, f.w, sq);
        mx = fmaxf(mx, fmaxf(fmaxf(f.x, f.y), fmaxf(f.z, f.w)));
    }
    #pragma unroll
    for (int o = 16; o; o >>= 1) {
        sum += __shfl_xor_sync(0xffffffffu, sum, o);
        sq  += __shfl_xor_sync(0xffffffffu, sq, o);
        mx   = fmaxf(mx, __shfl_xor_sync(0xffffffffu, mx, o));
    }

    float mean = sum * (1.0f / S_LEN);
    float var  = (sq - sum * mean) * (1.0f / (S_LEN - 1));  // ddof=1
    float tau  = fmaxf(1.0f / (1.0f + var), 0.3f);          // BASE=1, MIN=0.3
    float itau = 1.0f / tau;
    if (lane == 0) tau_out[row] = tau;

    float ls = 0.f;
    #pragma unroll
    for (int i = 0; i < 16; i++) {
        float4 f = d[i];
        f.x = __expf((f.x - mx) * itau);
        f.y = __expf((f.y - mx) * itau);
        f.z = __expf((f.z - mx) * itau);
        f.w = __expf((f.w - mx) * itau);
        d[i] = f;
        ls += f.x + f.y + f.z + f.w;
    }
    #pragma unroll
    for (int o = 16; o; o >>= 1) ls += __shfl_xor_sync(0xffffffffu, ls, o);
    const float rd = 1.0f / ls;

    #pragma unroll
    for (int i = 0; i < 16; i++) {
        float4 f = d[i];
        f.x = round_tf32(f.x * rd);
        f.y = round_tf32(f.y * rd);
        f.z = round_tf32(f.z * rd);
        f.w = round_tf32(f.w * rd);
        __stcs(&r4[lane + 32 * i], f);
    }
}

// -------------------------------------------------------------------------
// Kernel 3: out = attn @ V via single-term tf32 mma (m16n8k8).
// attn and V^T PRE-ROUNDED to tf32 -> raw f32 bits are valid operands.
// 4-STAGE cp.async pipeline over k=32 chunks (64 chunks), one sync/chunk.
// 256 thr, 8 warps (4m x 2n), warp tile 32x32. SMEM 108KB (4 bufs).
// smem per buffer: A[128][36] f32 | V[64][36] f32 (stride 36: banks
// (4r+c) mod 32 distinct for quad pattern -> conflict-free LDS).
// -------------------------------------------------------------------------
#define AVT_CH   36
#define AVT_BUF  27648             // (128*36 + 64*36) * 4 bytes
#define AVT_SMEM 110592            // 4 buffers

__global__ __launch_bounds__(256) void dsa_av_tf32(
    const float* __restrict__ attn, float* __restrict__ out)
{
    extern __shared__ __align__(16) float smf[];
    const uint32_t sb = smem_u32(smf);

    const int tid = threadIdx.x, lane = tid & 31, wid = tid >> 5;
    const int bh = blockIdx.y, qt = blockIdx.x;
    const int wm = wid >> 1, wn = wid & 1;

    const float* Ab = attn + ((size_t)bh * S_LEN + (size_t)qt * 128) * S_LEN;
    const float* Vt = g_vt + (size_t)bh * 64 * S_LEN;

    auto load_chunk = [&](int t, int buf) {
        uint32_t bp = sb + (uint32_t)buf * AVT_BUF;
        const int kk = t * 32;
        #pragma unroll
        for (int i = 0; i < 4; i++) {              // A: 128 x 32 f32
            int idx = tid + i * 256;
            int r = idx >> 3, seg = idx & 7;
            cpa16(bp + (uint32_t)(r * 144 + seg * 16),
                  Ab + (size_t)r * S_LEN + kk + seg * 4);
        }
        #pragma unroll
        for (int i = 0; i < 2; i++) {              // V^T: 64 x 32 f32
            int idx = tid + i * 256;
            int n = idx >> 3, seg = idx & 7;
            cpa16(bp + (uint32_t)(128 * 144 + n * 144 + seg * 16),
                  Vt + (size_t)n * S_LEN + kk + seg * 4);
        }
    };

    load_chunk(0, 0); cpa_commit();
    load_chunk(1, 1); cpa_commit();
    load_chunk(2, 2); cpa_commit();

    float acc[2][4][4] = {};
    const int ar = lane >> 2, ac = lane & 3;

    for (int t = 0; t < 64; t++) {
        if (t <= 61)      cpa_wait<2>();
        else if (t == 62) cpa_wait<1>();
        else              cpa_wait<0>();
        __syncthreads();

        const float* A0 = smf + (size_t)(t & 3) * (AVT_BUF / 4);
        const float* V0 = A0 + 128 * AVT_CH;

        #pragma unroll
        for (int s = 0; s < 4; s++) {
            // A tf32 fragments (raw bits; values pre-rounded to tf32)
            uint32_t av[2][4];
            #pragma unroll
            for (int mi = 0; mi < 2; mi++) {
                int r = wm * 32 + mi * 16 + ar;
                int c = s * 8 + ac;
                av[mi][0] = __float_as_uint(A0[r * AVT_CH + c]);
                av[mi][1] = __float_as_uint(A0[(r + 8) * AVT_CH + c]);
                av[mi][2] = __float_as_uint(A0[r * AVT_CH + c + 4]);
                av[mi][3] = __float_as_uint(A0[(r + 8) * AVT_CH + c + 4]);
            }
            // B tf32 fragments; V0 is [n][k], pre-rounded
            #pragma unroll
            for (int nj = 0; nj < 4; nj++) {
                int n = wn * 32 + nj * 8 + ar;
                int k = s * 8 + ac;
                uint32_t b0 = __float_as_uint(V0[n * AVT_CH + k]);
                uint32_t b1 = __float_as_uint(V0[n * AVT_CH + k + 4]);
                mma_tf32(acc[0][nj], av[0], b0, b1);
                mma_tf32(acc[1][nj], av[1], b0, b1);
            }
        }

        // refill buffer (t+3)%4 = buffer of chunk t-1 (its readers are done:
        // the sync at this iteration's top guaranteed compute(t-1) finished).
        if (t + 3 < 64) {
            load_chunk(t + 3, (t + 3) & 3);
            cpa_commit();
        }
    }

    const int qr = lane >> 2, qc = (lane & 3) * 2;
    float* Ob = out + ((size_t)bh * S_LEN + (size_t)qt * 128) * D_DIM;
    #pragma unroll
    for (int mi = 0; mi < 2; mi++) {
        #pragma unroll
        for (int nj = 0; nj < 4; nj++) {
            int row = wm * 32 + mi * 16 + qr;
            int col = wn * 32 + nj * 8 + qc;
            float2 v0 = make_float2(acc[mi][nj][0], acc[mi][nj][1]);
            float2 v1 = make_float2(acc[mi][nj][2], acc[mi][nj][3]);
            *(float2*)(Ob + (size_t)row * D_DIM + col) = v0;
            *(float2*)(Ob + (size_t)(row + 8) * D_DIM + col) = v1;
        }
    }
}

// -------------------------------------------------------------------------
extern "C" void kernel_launch(void* const* d_in, const int* in_sizes, int n_in,
                              void* d_out, int out_size)
{
    const float* q = (const float*)d_in[0];
    const float* k = (const float*)d_in[1];
    const float* v = (const float*)d_in[2];

    float* outp = (float*)d_out;                                   // BH*S*D
    float* attn = outp + (size_t)BH * S_LEN * D_DIM;               // BH*S*S
    float* tau  = attn + SELEM;                                    // BH*S

    cudaFuncSetAttribute(dsa_scores_kernel,
                         cudaFuncAttributeMaxDynamicSharedMemorySize, SC_SMEM);
    cudaFuncSetAttribute(dsa_av_tf32,
                         cudaFuncAttributeMaxDynamicSharedMemorySize, AVT_SMEM);

    dsa_prep<<<2048, 256>>>(q, k, v);
    dsa_scores_kernel<<<dim3(S_LEN / 128, BH), 512, SC_SMEM>>>(attn);
    dsa_softvar_kernel<<<BH * S_LEN / 8, 256>>>(attn, tau);
    dsa_av_tf32<<<dim3(S_LEN / 128, BH), 256, AVT_SMEM>>>(attn, outp);
}

// round 17
// speedup vs baseline: 1.0077x; 1.0077x over previous
#include <cuda_runtime.h>
#include <cuda_bf16.h>
#include <cstdint>

// DynamicSparseAttention: B=4,H=16,S=2048,D=64
// d_out layout (f32): [out: BH*S*D][attn: BH*S*S][tau: BH*S]
#define S_LEN 2048
#define D_DIM 64
#define BH    64
#define NELEM (BH * S_LEN * D_DIM)                 // 8388608
#define SELEM ((size_t)BH * S_LEN * S_LEN)         // 268435456

// pre-split bf16 hi/lo scratch for Q/K; f32(tf32-rounded) transposed V
__device__ __align__(16) __nv_bfloat16 g_qhi[NELEM];
__device__ __align__(16) __nv_bfloat16 g_qlo[NELEM];
__device__ __align__(16) __nv_bfloat16 g_khi[NELEM];
__device__ __align__(16) __nv_bfloat16 g_klo[NELEM];
__device__ __align__(16) float g_vt[NELEM];        // [bh][n=64][k=2048]

// ---------------------------------------------------------------- helpers
__device__ __forceinline__ uint32_t smem_u32(const void* p) {
    uint32_t a;
    asm("{ .reg .u64 t; cvta.to.shared.u64 t, %1; cvt.u32.u64 %0, t; }"
        : "=r"(a) : "l"(p));
    return a;
}

// 128B-row tile, 16B-chunk XOR swizzle
__device__ __forceinline__ uint32_t toff(int r, int ch) {
    return (uint32_t)(r * 128 + ((ch ^ (r & 7)) << 4));
}

__device__ __forceinline__ void ldmx4(uint32_t* r, uint32_t a) {
    asm volatile("ldmatrix.sync.aligned.m8n8.x4.shared.b16 {%0,%1,%2,%3}, [%4];"
        : "=r"(r[0]), "=r"(r[1]), "=r"(r[2]), "=r"(r[3]) : "r"(a));
}
__device__ __forceinline__ void mma_bf16(float* c, const uint32_t* a, const uint32_t* b) {
    asm volatile(
        "mma.sync.aligned.m16n8k16.row.col.f32.bf16.bf16.f32 "
        "{%0,%1,%2,%3}, {%4,%5,%6,%7}, {%8,%9}, {%0,%1,%2,%3};"
        : "+f"(c[0]), "+f"(c[1]), "+f"(c[2]), "+f"(c[3])
        : "r"(a[0]), "r"(a[1]), "r"(a[2]), "r"(a[3]), "r"(b[0]), "r"(b[1]));
}
__device__ __forceinline__ uint32_t cvt_tf32(float f) {
    uint32_t u;
    asm("cvt.rna.tf32.f32 %0, %1;" : "=r"(u) : "f"(f));
    return u;
}
__device__ __forceinline__ float round_tf32(float f) {
    return __uint_as_float(cvt_tf32(f));
}
__device__ __forceinline__ void mma_tf32(float* c, const uint32_t* a,
                                         uint32_t b0, uint32_t b1) {
    asm volatile(
        "mma.sync.aligned.m16n8k8.row.col.f32.tf32.tf32.f32 "
        "{%0,%1,%2,%3}, {%4,%5,%6,%7}, {%8,%9}, {%0,%1,%2,%3};"
        : "+f"(c[0]), "+f"(c[1]), "+f"(c[2]), "+f"(c[3])
        : "r"(a[0]), "r"(a[1]), "r"(a[2]), "r"(a[3]), "r"(b0), "r"(b1));
}

__device__ __forceinline__ void cpa16(uint32_t dst, const void* src) {
    asm volatile("cp.async.cg.shared.global [%0], [%1], 16;"
                 :: "r"(dst), "l"(__cvta_generic_to_global(src)));
}
__device__ __forceinline__ void cpa_commit() {
    asm volatile("cp.async.commit_group;");
}
template <int N>
__device__ __forceinline__ void cpa_wait() {
    asm volatile("cp.async.wait_group %0;" :: "n"(N));
}

__device__ __forceinline__ uint32_t bfpair(float a, float b) {
    __nv_bfloat162 t;
    t.x = __float2bfloat16(a);
    t.y = __float2bfloat16(b);
    return *reinterpret_cast<uint32_t*>(&t);
}
__device__ __forceinline__ void split2(float a, float b, uint32_t& h, uint32_t& l) {
    __nv_bfloat16 ha = __float2bfloat16(a), hb = __float2bfloat16(b);
    __nv_bfloat162 hp; hp.x = ha; hp.y = hb;
    h = *reinterpret_cast<uint32_t*>(&hp);
    l = bfpair(a - __bfloat162float(ha), b - __bfloat162float(hb));
}
__device__ __forceinline__ void split4(float4 f, uint2& hi, uint2& lo) {
    split2(f.x, f.y, hi.x, lo.x);
    split2(f.z, f.w, hi.y, lo.y);
}

// -------------------------------------------------------------------------
// Kernel 0: pre-split Q*0.125, K into bf16 hi/lo; transpose V -> g_vt
// (tf32-rounded, so AV needs no cvt).
// -------------------------------------------------------------------------
__global__ __launch_bounds__(256) void dsa_prep(
    const float* __restrict__ q, const float* __restrict__ k,
    const float* __restrict__ v)
{
    const int stride = gridDim.x * 256;
    const float4* q4 = (const float4*)q;
    const float4* k4 = (const float4*)k;
    const float4* v4 = (const float4*)v;
    uint2* qh = (uint2*)g_qhi; uint2* ql = (uint2*)g_qlo;
    uint2* kh = (uint2*)g_khi; uint2* kl = (uint2*)g_klo;

    for (int i = blockIdx.x * 256 + threadIdx.x; i < NELEM / 4; i += stride) {
        float4 fq = q4[i];
        fq.x *= 0.125f; fq.y *= 0.125f; fq.z *= 0.125f; fq.w *= 0.125f;
        uint2 hi, lo;
        split4(fq, hi, lo); qh[i] = hi; ql[i] = lo;
        split4(k4[i], hi, lo); kh[i] = hi; kl[i] = lo;

        // V transpose + tf32 rounding: i indexes [bh][kk][n4] float4
        float4 fv = v4[i];
        int bh = i >> 15;                 // / (2048*16)
        int rem = i & 32767;
        int kk = rem >> 4;
        int n4 = rem & 15;
        float* vt = g_vt + ((size_t)bh * 64 + n4 * 4) * S_LEN + kk;
        vt[0]          = round_tf32(fv.x);
        vt[S_LEN]      = round_tf32(fv.y);
        vt[2 * S_LEN]  = round_tf32(fv.z);
        vt[3 * S_LEN]  = round_tf32(fv.w);
    }
}

// -------------------------------------------------------------------------
// Kernel 1: raw scores = (Q*scale) K^T -> f32 attn buffer (pre-softmax).
// CTA = 128-row q-stripe over 16 k-tiles of 128. 512 thr, 16 warps (4m x 4n).
// A frags cached in regs; K tiles via cp.async double-buffered. SMEM 96KB.
// bf16 hi/lo 3-term split. Streaming stores (.cs) — read once much later.
// -------------------------------------------------------------------------
#define SC_SMEM 98304
__global__ __launch_bounds__(512) void dsa_scores_kernel(float* __restrict__ attn)
{
    extern __shared__ __align__(16) char sm[];
    const uint32_t sb = smem_u32(sm);
    const uint32_t QHI = 0, QLO = 16384;      // K bufs at 32768 + b*32768

    const int tid = threadIdx.x, lane = tid & 31, wid = tid >> 5;
    const int qt = blockIdx.x, bh = blockIdx.y;

    const __nv_bfloat16* Qh = g_qhi + ((size_t)bh * S_LEN + (size_t)qt * 128) * D_DIM;
    const __nv_bfloat16* Ql = g_qlo + ((size_t)bh * S_LEN + (size_t)qt * 128) * D_DIM;
    const __nv_bfloat16* Kh = g_khi + (size_t)bh * S_LEN * D_DIM;
    const __nv_bfloat16* Kl = g_klo + (size_t)bh * S_LEN * D_DIM;

    // group 0: Q hi/lo + K tile 0
    #pragma unroll
    for (int i = 0; i < 2; i++) {
        int idx = tid + i * 512;
        int r = idx >> 3, ch = idx & 7;
        uint32_t o = toff(r, ch);
        cpa16(sb + QHI + o, Qh + r * 64 + ch * 8);
        cpa16(sb + QLO + o, Ql + r * 64 + ch * 8);
        cpa16(sb + 32768 + o, Kh + r * 64 + ch * 8);
        cpa16(sb + 32768 + 16384 + o, Kl + r * 64 + ch * 8);
    }
    cpa_commit();
    // group 1: K tile 1
    #pragma unroll
    for (int i = 0; i < 2; i++) {
        int idx = tid + i * 512;
        int r = idx >> 3, ch = idx & 7;
        uint32_t o = toff(r, ch);
        cpa16(sb + 65536 + o, Kh + (size_t)(128 + r) * 64 + ch * 8);
        cpa16(sb + 65536 + 16384 + o, Kl + (size_t)(128 + r) * 64 + ch * 8);
    }
    cpa_commit();
    cpa_wait<1>();
    __syncthreads();

    const int wm = wid >> 2, wn = wid & 3;
    const int alr = lane & 7, alm = (lane >> 3) & 1, alk = lane >> 4;
    const int brow_off = ((lane >> 4) << 3) + (lane & 7);
    const int bchk_off = (lane >> 3) & 1;

    // A fragments cached in registers for the whole kernel
    uint32_t ah[4][2][4], al[4][2][4];
    #pragma unroll
    for (int ks = 0; ks < 4; ks++)
        #pragma unroll
        for (int mi = 0; mi < 2; mi++) {
            int row = wm * 32 + mi * 16 + alr + alm * 8;
            uint32_t o = toff(row, ks * 2 + alk);
            ldmx4(ah[ks][mi], sb + QHI + o);
            ldmx4(al[ks][mi], sb + QLO + o);
        }

    const int qr = lane >> 2, qc = (lane & 3) * 2;
    float* abase = attn + ((size_t)bh * S_LEN + (size_t)qt * 128) * S_LEN;

    for (int t = 0; t < 16; t++) {
        const uint32_t KB = sb + 32768 + (uint32_t)(t & 1) * 32768;

        float acc[2][4][4] = {};
        #pragma unroll
        for (int ks = 0; ks < 4; ks++) {
            uint32_t bh_[2][4], bl_[2][4];
            #pragma unroll
            for (int nj = 0; nj < 2; nj++) {
                int row = wn * 32 + nj * 16 + brow_off;
                uint32_t o = toff(row, ks * 2 + bchk_off);
                ldmx4(bh_[nj], KB + o);
                ldmx4(bl_[nj], KB + 16384 + o);
            }
            #pragma unroll
            for (int mi = 0; mi < 2; mi++)
                #pragma unroll
                for (int nj = 0; nj < 2; nj++) {
                    mma_bf16(acc[mi][2*nj],   ah[ks][mi], bh_[nj]);
                    mma_bf16(acc[mi][2*nj+1], ah[ks][mi], bh_[nj] + 2);
                }
            #pragma unroll
            for (int mi = 0; mi < 2; mi++)
                #pragma unroll
                for (int nj = 0; nj < 2; nj++) {
                    mma_bf16(acc[mi][2*nj],   ah[ks][mi], bl_[nj]);
                    mma_bf16(acc[mi][2*nj+1], ah[ks][mi], bl_[nj] + 2);
                }
            #pragma unroll
            for (int mi = 0; mi < 2; mi++)
                #pragma unroll
                for (int nj = 0; nj < 2; nj++) {
                    mma_bf16(acc[mi][2*nj],   al[ks][mi], bh_[nj]);
                    mma_bf16(acc[mi][2*nj+1], al[ks][mi], bh_[nj] + 2);
                }
        }

        float* base = abase + (size_t)t * 128;
        #pragma unroll
        for (int mi = 0; mi < 2; mi++) {
            #pragma unroll
            for (int ni = 0; ni < 4; ni++) {
                int row = wm * 32 + mi * 16 + qr;
                int col = wn * 32 + ni * 8 + qc;
                float2 v0 = make_float2(acc[mi][ni][0], acc[mi][ni][1]);
                float2 v1 = make_float2(acc[mi][ni][2], acc[mi][ni][3]);
                __stcs((float2*)(base + (size_t)row * S_LEN + col), v0);
                __stcs((float2*)(base + (size_t)(row + 8) * S_LEN + col), v1);
            }
        }
        __syncthreads();

        if (t + 2 < 16) {
            const __nv_bfloat16* th = Kh + (size_t)(t + 2) * 128 * 64;
            const __nv_bfloat16* tl = Kl + (size_t)(t + 2) * 128 * 64;
            uint32_t dst = sb + 32768 + (uint32_t)(t & 1) * 32768;
            #pragma unroll
            for (int i = 0; i < 2; i++) {
                int idx = tid + i * 512;
                int r = idx >> 3, ch = idx & 7;
                uint32_t o = toff(r, ch);
                cpa16(dst + o, th + r * 64 + ch * 8);
                cpa16(dst + 16384 + o, tl + r * 64 + ch * 8);
            }
            cpa_commit();
            cpa_wait<1>();
        } else {
            cpa_wait<0>();
        }
        __syncthreads();
    }
}

// -------------------------------------------------------------------------
// Kernel 2: per-row variance (ddof=1) -> tau -> softmax(scores/tau) in place.
// Warp-per-row, row in registers. Output values tf32-ROUNDED (still valid
// f32; lets AV consume raw bits with zero cvt). Streaming ld/st hints.
// -------------------------------------------------------------------------
__global__ __launch_bounds__(256, 2) void dsa_softvar_kernel(
    float* __restrict__ attn, float* __restrict__ tau_out)
{
    const int lane = threadIdx.x & 31;
    const int w = threadIdx.x >> 5;
    const size_t row = (size_t)blockIdx.x * 8 + w;
    float4* r4 = (float4*)(attn + row * S_LEN);

    float4 d[16];
    float sum = 0.f, sq = 0.f, mx = -3.402823466e38f;
    #pragma unroll
    for (int i = 0; i < 16; i++) {
        float4 f = __ldcs(&r4[lane + 32 * i]);
        d[i] = f;
        sum += f.x + f.y + f.z + f.w;
        sq = fmaf(f.x, f.x, sq); sq = fmaf(f.y, f.y, sq);
        sq = fmaf(f.z, f.z, sq); sq = fmaf(f.w, f.w, sq);
        mx = fmaxf(mx, fmaxf(fmaxf(f.x, f.y), fmaxf(f.z, f.w)));
    }
    #pragma unroll
    for (int o = 16; o; o >>= 1) {
        sum += __shfl_xor_sync(0xffffffffu, sum, o);
        sq  += __shfl_xor_sync(0xffffffffu, sq, o);
        mx   = fmaxf(mx, __shfl_xor_sync(0xffffffffu, mx, o));
    }

    float mean = sum * (1.0f / S_LEN);
    float var  = (sq - sum * mean) * (1.0f / (S_LEN - 1));  // ddof=1
    float tau  = fmaxf(1.0f / (1.0f + var), 0.3f);          // BASE=1, MIN=0.3
    float itau = 1.0f / tau;
    if (lane == 0) tau_out[row] = tau;

    float ls = 0.f;
    #pragma unroll
    for (int i = 0; i < 16; i++) {
        float4 f = d[i];
        f.x = __expf((f.x - mx) * itau);
        f.y = __expf((f.y - mx) * itau);
        f.z = __expf((f.z - mx) * itau);
        f.w = __expf((f.w - mx) * itau);
        d[i] = f;
        ls += f.x + f.y + f.z + f.w;
    }
    #pragma unroll
    for (int o = 16; o; o >>= 1) ls += __shfl_xor_sync(0xffffffffu, ls, o);
    const float rd = 1.0f / ls;

    #pragma unroll
    for (int i = 0; i < 16; i++) {
        float4 f = d[i];
        f.x = round_tf32(f.x * rd);
        f.y = round_tf32(f.y * rd);
        f.z = round_tf32(f.z * rd);
        f.w = round_tf32(f.w * rd);
        __stcs(&r4[lane + 32 * i], f);
    }
}

// -------------------------------------------------------------------------
// Kernel 3: out = attn @ V via single-term tf32 mma (m16n8k8).
// attn and V^T PRE-ROUNDED to tf32 -> raw f32 bits are valid operands.
// k=32 chunks, 2 buffers (55KB) -> 4 CTAs/SM for cross-CTA latency hiding.
// 256 thr, 8 warps (4m x 2n), warp tile 32x32.
// smem per buffer: A[128][36] f32 | V[64][36] f32 (stride 36 conflict-free).
// -------------------------------------------------------------------------
#define AVT_CH   36
#define AVT_BUF  27648             // (128*36 + 64*36) * 4 bytes
#define AVT_SMEM 55296             // 2 buffers

__global__ __launch_bounds__(256, 4) void dsa_av_tf32(
    const float* __restrict__ attn, float* __restrict__ out)
{
    extern __shared__ __align__(16) float smf[];
    const uint32_t sb = smem_u32(smf);

    const int tid = threadIdx.x, lane = tid & 31, wid = tid >> 5;
    const int bh = blockIdx.y, qt = blockIdx.x;
    const int wm = wid >> 1, wn = wid & 1;

    const float* Ab = attn + ((size_t)bh * S_LEN + (size_t)qt * 128) * S_LEN;
    const float* Vt = g_vt + (size_t)bh * 64 * S_LEN;

    auto load_chunk = [&](int t, int buf) {
        uint32_t bp = sb + (uint32_t)buf * AVT_BUF;
        const int kk = t * 32;
        #pragma unroll
        for (int i = 0; i < 4; i++) {              // A: 128 x 32 f32
            int idx = tid + i * 256;
            int r = idx >> 3, seg = idx & 7;
            cpa16(bp + (uint32_t)(r * 144 + seg * 16),
                  Ab + (size_t)r * S_LEN + kk + seg * 4);
        }
        #pragma unroll
        for (int i = 0; i < 2; i++) {              // V^T: 64 x 32 f32
            int idx = tid + i * 256;
            int n = idx >> 3, seg = idx & 7;
            cpa16(bp + (uint32_t)(128 * 144 + n * 144 + seg * 16),
                  Vt + (size_t)n * S_LEN + kk + seg * 4);
        }
    };

    load_chunk(0, 0); cpa_commit();
    load_chunk(1, 1); cpa_commit();
    cpa_wait<1>();
    __syncthreads();

    float acc[2][4][4] = {};
    const int ar = lane >> 2, ac = lane & 3;

    for (int t = 0; t < 64; t++) {
        const float* A0 = smf + (size_t)(t & 1) * (AVT_BUF / 4);
        const float* V0 = A0 + 128 * AVT_CH;

        #pragma unroll
        for (int s = 0; s < 4; s++) {
            // A tf32 fragments (raw bits; values pre-rounded to tf32)
            uint32_t av[2][4];
            #pragma unroll
            for (int mi = 0; mi < 2; mi++) {
                int r = wm * 32 + mi * 16 + ar;
                int c = s * 8 + ac;
                av[mi][0] = __float_as_uint(A0[r * AVT_CH + c]);
                av[mi][1] = __float_as_uint(A0[(r + 8) * AVT_CH + c]);
                av[mi][2] = __float_as_uint(A0[r * AVT_CH + c + 4]);
                av[mi][3] = __float_as_uint(A0[(r + 8) * AVT_CH + c + 4]);
            }
            // B tf32 fragments; V0 is [n][k], pre-rounded
            #pragma unroll
            for (int nj = 0; nj < 4; nj++) {
                int n = wn * 32 + nj * 8 + ar;
                int k = s * 8 + ac;
                uint32_t b0 = __float_as_uint(V0[n * AVT_CH + k]);
                uint32_t b1 = __float_as_uint(V0[n * AVT_CH + k + 4]);
                mma_tf32(acc[0][nj], av[0], b0, b1);
                mma_tf32(acc[1][nj], av[1], b0, b1);
            }
        }
        __syncthreads();

        if (t + 2 < 64) {
            load_chunk(t + 2, t & 1);
            cpa_commit();
        }
        if (t + 1 < 64) {
            if (t + 2 < 64) { cpa_wait<1>(); } else { cpa_wait<0>(); }
            __syncthreads();
        }
    }

    const int qr = lane >> 2, qc = (lane & 3) * 2;
    float* Ob = out + ((size_t)bh * S_LEN + (size_t)qt * 128) * D_DIM;
    #pragma unroll
    for (int mi = 0; mi < 2; mi++) {
        #pragma unroll
        for (int nj = 0; nj < 4; nj++) {
            int row = wm * 32 + mi * 16 + qr;
            int col = wn * 32 + nj * 8 + qc;
            float2 v0 = make_float2(acc[mi][nj][0], acc[mi][nj][1]);
            float2 v1 = make_float2(acc[mi][nj][2], acc[mi][nj][3]);
            *(float2*)(Ob + (size_t)row * D_DIM + col) = v0;
            *(float2*)(Ob + (size_t)(row + 8) * D_DIM + col) = v1;
        }
    }
}

// -------------------------------------------------------------------------
extern "C" void kernel_launch(void* const* d_in, const int* in_sizes, int n_in,
                              void* d_out, int out_size)
{
    const float* q = (const float*)d_in[0];
    const float* k = (const float*)d_in[1];
    const float* v = (const float*)d_in[2];

    float* outp = (float*)d_out;                                   // BH*S*D
    float* attn = outp + (size_t)BH * S_LEN * D_DIM;               // BH*S*S
    float* tau  = attn + SELEM;                                    // BH*S

    cudaFuncSetAttribute(dsa_scores_kernel,
                         cudaFuncAttributeMaxDynamicSharedMemorySize, SC_SMEM);
    cudaFuncSetAttribute(dsa_av_tf32,
                         cudaFuncAttributeMaxDynamicSharedMemorySize, AVT_SMEM);

    dsa_prep<<<2048, 256>>>(q, k, v);
    dsa_scores_kernel<<<dim3(S_LEN / 128, BH), 512, SC_SMEM>>>(attn);
    dsa_softvar_kernel<<<BH * S_LEN / 8, 256>>>(attn, tau);
    dsa_av_tf32<<<dim3(S_LEN / 128, BH), 256, AVT_SMEM>>>(attn, outp);
}